// round 1
// baseline (speedup 1.0000x reference)
#include <cuda_runtime.h>
#include <cstdint>

#define MTOK   8192
#define DMODEL 2048
#define DFF    8192
#define NGX    (DMODEL/64)   // 32 groups per row for x
#define NGH    (DFF/64)      // 128 groups per row for h

// ---------------- scratch (device globals; no allocations allowed) ----------
__device__ int8_t g_w1s[DFF*DMODEL];
__device__ int8_t g_w2s[DFF*DMODEL];
__device__ int8_t g_w3s[DMODEL*DFF];
__device__ int8_t g_xq [MTOK*DMODEL];
__device__ float  g_sx [MTOK*NGX];
__device__ float  g_h  [(size_t)MTOK*DFF];     // 256 MB fp32 intermediate
__device__ int8_t g_hq [MTOK*DFF];
__device__ float  g_sh [MTOK*NGH];
__device__ float  g_partial[2048];
__device__ float  g_wscale[3];                 // mean|w1|, mean|w2|, mean|w3|

// ---------------- small helpers --------------------------------------------
__device__ __forceinline__ void ldsm4(uint32_t r[4], uint32_t addr){
  asm volatile("ldmatrix.sync.aligned.m8n8.x4.shared.b16 {%0,%1,%2,%3},[%4];"
               : "=r"(r[0]),"=r"(r[1]),"=r"(r[2]),"=r"(r[3]) : "r"(addr));
}
__device__ __forceinline__ void ldsm2(uint32_t r[2], uint32_t addr){
  asm volatile("ldmatrix.sync.aligned.m8n8.x2.shared.b16 {%0,%1},[%2];"
               : "=r"(r[0]),"=r"(r[1]) : "r"(addr));
}
__device__ __forceinline__ void imma(int d[4], const uint32_t a[4], const uint32_t b[2]){
  asm volatile("mma.sync.aligned.m16n8k32.row.col.s32.s8.s8.s32 "
               "{%0,%1,%2,%3},{%4,%5,%6,%7},{%8,%9},{%0,%1,%2,%3};"
               : "+r"(d[0]),"+r"(d[1]),"+r"(d[2]),"+r"(d[3])
               : "r"(a[0]),"r"(a[1]),"r"(a[2]),"r"(a[3]),"r"(b[0]),"r"(b[1]));
}
__device__ __forceinline__ void cpa16(uint32_t d, const void* s){
  asm volatile("cp.async.cg.shared.global [%0],[%1],16;" :: "r"(d),"l"(s));
}
__device__ __forceinline__ void cpa4(uint32_t d, const void* s){
  asm volatile("cp.async.ca.shared.global [%0],[%1],4;" :: "r"(d),"l"(s));
}

// ---------------- mean(|w|) : deterministic two-pass ------------------------
__global__ void absmean_partial(const float4* __restrict__ w, int n4){
  float s = 0.f;
  for (int i = blockIdx.x*blockDim.x + threadIdx.x; i < n4; i += gridDim.x*blockDim.x){
    float4 v = w[i];
    s += fabsf(v.x)+fabsf(v.y)+fabsf(v.z)+fabsf(v.w);
  }
  __shared__ float sm[256];
  sm[threadIdx.x]=s; __syncthreads();
  for (int o=128;o>0;o>>=1){ if(threadIdx.x<o) sm[threadIdx.x]+=sm[threadIdx.x+o]; __syncthreads(); }
  if (threadIdx.x==0) g_partial[blockIdx.x]=sm[0];
}
__global__ void absmean_final(int nblocks, float inv_n, int idx){
  __shared__ float sm[256];
  float s=0.f;
  for (int i=threadIdx.x;i<nblocks;i+=256) s+=g_partial[i];
  sm[threadIdx.x]=s; __syncthreads();
  for (int o=128;o>0;o>>=1){ if(threadIdx.x<o) sm[threadIdx.x]+=sm[threadIdx.x+o]; __syncthreads(); }
  if (threadIdx.x==0) g_wscale[idx]=sm[0]*inv_n;
}

// ---------------- sign(w) -> int8 ±1 ---------------------------------------
__global__ void sign_kernel(const float4* __restrict__ w, char4* __restrict__ o, int n4){
  int i = blockIdx.x*blockDim.x + threadIdx.x, st = gridDim.x*blockDim.x;
  for (; i<n4; i+=st){
    float4 v = w[i]; char4 c;
    c.x = (char)((v.x>0.f)-(v.x<0.f));
    c.y = (char)((v.y>0.f)-(v.y<0.f));
    c.z = (char)((v.z>0.f)-(v.z<0.f));
    c.w = (char)((v.w>0.f)-(v.w<0.f));
    o[i]=c;
  }
}

// ---------------- per-64-group int8 activation quant -------------------------
// One warp per group of 64 contiguous floats. Exact replica of reference math:
// s = max(max|x|, 1e-5); q = rint(x * (127/s)); dequant scale stored = s/127.
__global__ void quant_kernel(const float2* __restrict__ src, char2* __restrict__ q,
                             float* __restrict__ sc, int ngroups){
  int w    = (blockIdx.x*blockDim.x + threadIdx.x)>>5;
  int lane = threadIdx.x & 31;
  int nw   = (gridDim.x*blockDim.x)>>5;
  for (int g=w; g<ngroups; g+=nw){
    float2 v = src[g*32 + lane];
    float m = fmaxf(fabsf(v.x), fabsf(v.y));
#pragma unroll
    for (int o=16;o;o>>=1) m = fmaxf(m, __shfl_xor_sync(0xffffffffu, m, o));
    float s   = fmaxf(m, 1e-5f);
    float inv = 127.0f / s;
    char2 c;
    c.x = (signed char)__float2int_rn(v.x*inv);
    c.y = (signed char)__float2int_rn(v.y*inv);
    q[g*32 + lane] = c;
    if (lane==0) sc[g] = s * (1.0f/127.0f);
  }
}

// ---------------- grouped int8 GEMM ------------------------------------------
// MODE 0: dual-B (w1,w2) fused, SwiGLU epilogue -> g_h  (KTOT=2048)
// MODE 1: single-B (w3), scale epilogue -> C            (KTOT=8192)
// CTA tile 128x128, 8 warps (2x4), warp tile 64x32, K-stage = 64 = one group.
template<int NB, int KTOT>
__device__ __forceinline__ void load_stage(uint32_t st, const int8_t* A, const float* sA,
    const int8_t* B1, const int8_t* B2, int m0, int n0, int g, int tid)
{
#pragma unroll
  for (int i=0;i<2;i++){
    int c = tid + i*256, r = c>>2, kc = c&3;
    cpa16(st + r*64 + ((kc ^ ((r>>1)&3))<<4),
          A + (size_t)(m0+r)*KTOT + g*64 + kc*16);
  }
#pragma unroll
  for (int b=0;b<NB;b++){
    const int8_t* Bp = b ? B2 : B1;
#pragma unroll
    for (int i=0;i<2;i++){
      int c = tid + i*256, r = c>>2, kc = c&3;
      cpa16(st + 128*64*(1+b) + r*64 + ((kc ^ ((r>>1)&3))<<4),
            Bp + (size_t)(n0+r)*KTOT + g*64 + kc*16);
    }
  }
  if (tid < 128) cpa4(st + 128*64*(1+NB) + tid*4, sA + (size_t)(m0+tid)*KTOT/64 + g);
  asm volatile("cp.async.commit_group;");
}

template<int MODE, int KTOT>
__global__ void __launch_bounds__(256,1) gemm_s8(
    const int8_t* __restrict__ A, const float* __restrict__ sA,
    const int8_t* __restrict__ B1, const int8_t* __restrict__ B2,
    float* __restrict__ C)
{
  constexpr int NB    = (MODE==0) ? 2 : 1;
  constexpr int NG    = KTOT/64;
  constexpr int STAGE = 128*64*(1+NB) + 128*4;
  extern __shared__ char smem[];
  const uint32_t sb = (uint32_t)__cvta_generic_to_shared(smem);
  const int tid = threadIdx.x, lane = tid&31, wid = tid>>5;
  const int m0 = blockIdx.y*128, n0 = blockIdx.x*128;
  const int wm = (wid>>2)*64, wn = (wid&3)*32;

  // ldmatrix per-lane address components (swizzle: 16B chunk ^= (row>>1)&3)
  const int ar   = (lane&7) + ((lane>>3)&1)*8;   // A row within m16 tile
  const int acb  = (lane>>4)&1;                  // A 16B-chunk base
  const int aswz = (ar>>1)&3;
  const int br   = lane&7;                       // B row within n8 tile
  const int bcb  = (lane>>3)&1;
  const int bswz = (br>>1)&3;

  float f1[4][4][4]; float f2[4][4][4];
#pragma unroll
  for (int i=0;i<4;i++)
#pragma unroll
    for (int j=0;j<4;j++)
#pragma unroll
      for (int k=0;k<4;k++){ f1[i][j][k]=0.f; if (MODE==0) f2[i][j][k]=0.f; }

  load_stage<NB,KTOT>(sb, A, sA, B1, B2, m0, n0, 0, tid);

#pragma unroll 1
  for (int g=0; g<NG; ++g){
    const int s = g&1;
    if (g+1 < NG){
      load_stage<NB,KTOT>(sb + (s^1)*STAGE, A, sA, B1, B2, m0, n0, g+1, tid);
      asm volatile("cp.async.wait_group 1;");
    } else {
      asm volatile("cp.async.wait_group 0;");
    }
    __syncthreads();

    const uint32_t st = sb + s*STAGE;
    const float* sf = (const float*)(smem + s*STAGE + 128*64*(1+NB));
    float sc[4][2];
#pragma unroll
    for (int mt=0;mt<4;mt++){
      sc[mt][0] = sf[wm + mt*16 + (lane>>2)];
      sc[mt][1] = sf[wm + mt*16 + (lane>>2) + 8];
    }

    uint32_t a[2][4][4];
#pragma unroll
    for (int ks=0;ks<2;ks++)
#pragma unroll
      for (int mt=0;mt<4;mt++)
        ldsm4(a[ks][mt], st + (wm+mt*16+ar)*64 + (((acb+ks*2)^aswz)<<4));

    // ---- GEMM vs B1 ----
    {
      uint32_t bfr[2][4][2];
#pragma unroll
      for (int ks=0;ks<2;ks++)
#pragma unroll
        for (int nt=0;nt<4;nt++)
          ldsm2(bfr[ks][nt], st + 128*64 + (wn+nt*8+br)*64 + (((bcb+ks*2)^bswz)<<4));
#pragma unroll
      for (int mt=0;mt<4;mt++)
#pragma unroll
        for (int nt=0;nt<4;nt++){
          int d[4]={0,0,0,0};
          imma(d, a[0][mt], bfr[0][nt]);
          imma(d, a[1][mt], bfr[1][nt]);
          f1[mt][nt][0] += sc[mt][0]*(float)d[0];
          f1[mt][nt][1] += sc[mt][0]*(float)d[1];
          f1[mt][nt][2] += sc[mt][1]*(float)d[2];
          f1[mt][nt][3] += sc[mt][1]*(float)d[3];
        }
    }
    // ---- GEMM vs B2 (MODE 0 only) ----
    if (MODE==0){
      uint32_t bfr[2][4][2];
#pragma unroll
      for (int ks=0;ks<2;ks++)
#pragma unroll
        for (int nt=0;nt<4;nt++)
          ldsm2(bfr[ks][nt], st + 128*64*2 + (wn+nt*8+br)*64 + (((bcb+ks*2)^bswz)<<4));
#pragma unroll
      for (int mt=0;mt<4;mt++)
#pragma unroll
        for (int nt=0;nt<4;nt++){
          int d[4]={0,0,0,0};
          imma(d, a[0][mt], bfr[0][nt]);
          imma(d, a[1][mt], bfr[1][nt]);
          f2[mt][nt][0] += sc[mt][0]*(float)d[0];
          f2[mt][nt][1] += sc[mt][0]*(float)d[1];
          f2[mt][nt][2] += sc[mt][1]*(float)d[2];
          f2[mt][nt][3] += sc[mt][1]*(float)d[3];
        }
    }
    __syncthreads();
  }

  // ---------------- epilogue ----------------
  if (MODE==0){
    const float c1 = g_wscale[0], c2 = g_wscale[1];
#pragma unroll
    for (int mt=0;mt<4;mt++)
#pragma unroll
      for (int nt=0;nt<4;nt++)
#pragma unroll
        for (int hr=0;hr<2;hr++){
          int r    = m0 + wm + mt*16 + (lane>>2) + hr*8;
          int cidx = n0 + wn + nt*8 + (lane&3)*2;
          float u0 = c1*f1[mt][nt][hr*2+0], u1 = c1*f1[mt][nt][hr*2+1];
          float v0 = c2*f2[mt][nt][hr*2+0], v1 = c2*f2[mt][nt][hr*2+1];
          float h0 = u0/(1.f+expf(-u0))*v0;
          float h1 = u1/(1.f+expf(-u1))*v1;
          *(float2*)&g_h[(size_t)r*DFF + cidx] = make_float2(h0,h1);
        }
  } else {
    const float c3 = g_wscale[2];
#pragma unroll
    for (int mt=0;mt<4;mt++)
#pragma unroll
      for (int nt=0;nt<4;nt++)
#pragma unroll
        for (int hr=0;hr<2;hr++){
          int r    = m0 + wm + mt*16 + (lane>>2) + hr*8;
          int cidx = n0 + wn + nt*8 + (lane&3)*2;
          *(float2*)&C[(size_t)r*DMODEL + cidx] =
              make_float2(c3*f1[mt][nt][hr*2+0], c3*f1[mt][nt][hr*2+1]);
        }
  }
}

// ---------------- host launcher ---------------------------------------------
extern "C" void kernel_launch(void* const* d_in, const int* in_sizes, int n_in,
                              void* d_out, int out_size)
{
  const float* x  = (const float*)d_in[0];
  const float* w1 = (const float*)d_in[1];
  const float* w2 = (const float*)d_in[2];
  const float* w3 = (const float*)d_in[3];

  void *w1s,*w2s,*w3s,*xq,*sx,*h,*hq,*sh;
  cudaGetSymbolAddress(&w1s, g_w1s);
  cudaGetSymbolAddress(&w2s, g_w2s);
  cudaGetSymbolAddress(&w3s, g_w3s);
  cudaGetSymbolAddress(&xq , g_xq );
  cudaGetSymbolAddress(&sx , g_sx );
  cudaGetSymbolAddress(&h  , g_h  );
  cudaGetSymbolAddress(&hq , g_hq );
  cudaGetSymbolAddress(&sh , g_sh );

  const int NW12 = DFF*DMODEL;     // 16.7M
  const int NW3  = DMODEL*DFF;

  // mean|w| (deterministic two-pass), sequential reuse of g_partial
  absmean_partial<<<2048,256>>>((const float4*)w1, NW12/4);
  absmean_final  <<<1,256>>>(2048, 1.0f/(float)NW12, 0);
  absmean_partial<<<2048,256>>>((const float4*)w2, NW12/4);
  absmean_final  <<<1,256>>>(2048, 1.0f/(float)NW12, 1);
  absmean_partial<<<2048,256>>>((const float4*)w3, NW3/4);
  absmean_final  <<<1,256>>>(2048, 1.0f/(float)NW3, 2);

  // sign-pack weights
  sign_kernel<<<4096,256>>>((const float4*)w1, (char4*)w1s, NW12/4);
  sign_kernel<<<4096,256>>>((const float4*)w2, (char4*)w2s, NW12/4);
  sign_kernel<<<4096,256>>>((const float4*)w3, (char4*)w3s, NW3/4);

  // quantize x
  quant_kernel<<<2048,256>>>((const float2*)x, (char2*)xq, (float*)sx, MTOK*NGX);

  // fused GEMM1+2 + SwiGLU -> g_h
  constexpr int SM0 = 2*(128*64*3 + 128*4);
  cudaFuncSetAttribute(gemm_s8<0,DMODEL>, cudaFuncAttributeMaxDynamicSharedMemorySize, SM0);
  gemm_s8<0,DMODEL><<<dim3(DFF/128, MTOK/128), 256, SM0>>>(
      (const int8_t*)xq, (const float*)sx,
      (const int8_t*)w1s, (const int8_t*)w2s, nullptr);

  // quantize h
  quant_kernel<<<4096,256>>>((const float2*)h, (char2*)hq, (float*)sh, MTOK*NGH);

  // GEMM3 -> out
  constexpr int SM1 = 2*(128*64*2 + 128*4);
  cudaFuncSetAttribute(gemm_s8<1,DFF>, cudaFuncAttributeMaxDynamicSharedMemorySize, SM1);
  gemm_s8<1,DFF><<<dim3(DMODEL/128, MTOK/128), 256, SM1>>>(
      (const int8_t*)hq, (const float*)sh,
      (const int8_t*)w3s, nullptr, (float*)d_out);
}

// round 2
// speedup vs baseline: 1.0006x; 1.0006x over previous
#include <cuda_runtime.h>
#include <cstdint>

#define MTOK   8192
#define DMODEL 2048
#define DFF    8192
#define NGX    (DMODEL/64)   // 32 groups per row for x
#define NGH    (DFF/64)      // 128 groups per row for h

// ---------------- scratch (device globals; no allocations allowed) ----------
__device__ int8_t g_w1s[DFF*DMODEL];
__device__ int8_t g_w2s[DFF*DMODEL];
__device__ int8_t g_w3s[DMODEL*DFF];
__device__ int8_t g_xq [MTOK*DMODEL];
__device__ float  g_sx [MTOK*NGX];
__device__ float  g_h  [(size_t)MTOK*DFF];     // 256 MB fp32 intermediate
__device__ int8_t g_hq [MTOK*DFF];
__device__ float  g_sh [MTOK*NGH];
__device__ float  g_partial[2048];
__device__ float  g_wscale[3];                 // mean|w1|, mean|w2|, mean|w3|

// ---------------- small helpers --------------------------------------------
__device__ __forceinline__ void ldsm4(uint32_t r[4], uint32_t addr){
  asm volatile("ldmatrix.sync.aligned.m8n8.x4.shared.b16 {%0,%1,%2,%3},[%4];"
               : "=r"(r[0]),"=r"(r[1]),"=r"(r[2]),"=r"(r[3]) : "r"(addr));
}
__device__ __forceinline__ void ldsm2(uint32_t r[2], uint32_t addr){
  asm volatile("ldmatrix.sync.aligned.m8n8.x2.shared.b16 {%0,%1},[%2];"
               : "=r"(r[0]),"=r"(r[1]) : "r"(addr));
}
__device__ __forceinline__ void imma(int d[4], const uint32_t a[4], const uint32_t b[2]){
  asm volatile("mma.sync.aligned.m16n8k32.row.col.s32.s8.s8.s32 "
               "{%0,%1,%2,%3},{%4,%5,%6,%7},{%8,%9},{%0,%1,%2,%3};"
               : "+r"(d[0]),"+r"(d[1]),"+r"(d[2]),"+r"(d[3])
               : "r"(a[0]),"r"(a[1]),"r"(a[2]),"r"(a[3]),"r"(b[0]),"r"(b[1]));
}
__device__ __forceinline__ void cpa16(uint32_t d, const void* s){
  asm volatile("cp.async.cg.shared.global [%0],[%1],16;" :: "r"(d),"l"(s));
}
__device__ __forceinline__ void cpa4(uint32_t d, const void* s){
  asm volatile("cp.async.ca.shared.global [%0],[%1],4;" :: "r"(d),"l"(s));
}

// ---------------- mean(|w|) : deterministic two-pass ------------------------
__global__ void absmean_partial(const float4* __restrict__ w, int n4){
  float s = 0.f;
  for (int i = blockIdx.x*blockDim.x + threadIdx.x; i < n4; i += gridDim.x*blockDim.x){
    float4 v = w[i];
    s += fabsf(v.x)+fabsf(v.y)+fabsf(v.z)+fabsf(v.w);
  }
  __shared__ float sm[256];
  sm[threadIdx.x]=s; __syncthreads();
  for (int o=128;o>0;o>>=1){ if(threadIdx.x<o) sm[threadIdx.x]+=sm[threadIdx.x+o]; __syncthreads(); }
  if (threadIdx.x==0) g_partial[blockIdx.x]=sm[0];
}
__global__ void absmean_final(int nblocks, float inv_n, int idx){
  __shared__ float sm[256];
  float s=0.f;
  for (int i=threadIdx.x;i<nblocks;i+=256) s+=g_partial[i];
  sm[threadIdx.x]=s; __syncthreads();
  for (int o=128;o>0;o>>=1){ if(threadIdx.x<o) sm[threadIdx.x]+=sm[threadIdx.x+o]; __syncthreads(); }
  if (threadIdx.x==0) g_wscale[idx]=sm[0]*inv_n;
}

// ---------------- sign(w) -> int8 ±1 ---------------------------------------
__global__ void sign_kernel(const float4* __restrict__ w, char4* __restrict__ o, int n4){
  int i = blockIdx.x*blockDim.x + threadIdx.x, st = gridDim.x*blockDim.x;
  for (; i<n4; i+=st){
    float4 v = w[i]; char4 c;
    c.x = (char)((v.x>0.f)-(v.x<0.f));
    c.y = (char)((v.y>0.f)-(v.y<0.f));
    c.z = (char)((v.z>0.f)-(v.z<0.f));
    c.w = (char)((v.w>0.f)-(v.w<0.f));
    o[i]=c;
  }
}

// ---------------- per-64-group int8 activation quant -------------------------
// One warp per group of 64 contiguous floats. Exact replica of reference math:
// s = max(max|x|, 1e-5); q = rint(x * (127/s)); dequant scale stored = s/127.
__global__ void quant_kernel(const float2* __restrict__ src, char2* __restrict__ q,
                             float* __restrict__ sc, int ngroups){
  int w    = (blockIdx.x*blockDim.x + threadIdx.x)>>5;
  int lane = threadIdx.x & 31;
  int nw   = (gridDim.x*blockDim.x)>>5;
  for (int g=w; g<ngroups; g+=nw){
    float2 v = src[g*32 + lane];
    float m = fmaxf(fabsf(v.x), fabsf(v.y));
#pragma unroll
    for (int o=16;o;o>>=1) m = fmaxf(m, __shfl_xor_sync(0xffffffffu, m, o));
    float s   = fmaxf(m, 1e-5f);
    float inv = 127.0f / s;
    char2 c;
    c.x = (signed char)__float2int_rn(v.x*inv);
    c.y = (signed char)__float2int_rn(v.y*inv);
    q[g*32 + lane] = c;
    if (lane==0) sc[g] = s * (1.0f/127.0f);
  }
}

// ---------------- grouped int8 GEMM ------------------------------------------
// MODE 0: dual-B (w1,w2) fused, SwiGLU epilogue -> g_h  (KTOT=2048)
// MODE 1: single-B (w3), scale epilogue -> C            (KTOT=8192)
// CTA tile 128x128, 8 warps (2x4), warp tile 64x32, K-stage = 64 = one group.
template<int NB, int KTOT>
__device__ __forceinline__ void load_stage(uint32_t st, const int8_t* A, const float* sA,
    const int8_t* B1, const int8_t* B2, int m0, int n0, int g, int tid)
{
#pragma unroll
  for (int i=0;i<2;i++){
    int c = tid + i*256, r = c>>2, kc = c&3;
    cpa16(st + r*64 + ((kc ^ ((r>>1)&3))<<4),
          A + (size_t)(m0+r)*KTOT + g*64 + kc*16);
  }
#pragma unroll
  for (int b=0;b<NB;b++){
    const int8_t* Bp = b ? B2 : B1;
#pragma unroll
    for (int i=0;i<2;i++){
      int c = tid + i*256, r = c>>2, kc = c&3;
      cpa16(st + 128*64*(1+b) + r*64 + ((kc ^ ((r>>1)&3))<<4),
            Bp + (size_t)(n0+r)*KTOT + g*64 + kc*16);
    }
  }
  if (tid < 128) cpa4(st + 128*64*(1+NB) + tid*4, sA + (size_t)(m0+tid)*KTOT/64 + g);
  asm volatile("cp.async.commit_group;");
}

template<int MODE, int KTOT>
__global__ void __launch_bounds__(256,1) gemm_s8(
    const int8_t* __restrict__ A, const float* __restrict__ sA,
    const int8_t* __restrict__ B1, const int8_t* __restrict__ B2,
    float* __restrict__ C)
{
  constexpr int NB    = (MODE==0) ? 2 : 1;
  constexpr int NG    = KTOT/64;
  constexpr int STAGE = 128*64*(1+NB) + 128*4;
  extern __shared__ char smem[];
  const uint32_t sb = (uint32_t)__cvta_generic_to_shared(smem);
  const int tid = threadIdx.x, lane = tid&31, wid = tid>>5;
  const int m0 = blockIdx.y*128, n0 = blockIdx.x*128;
  const int wm = (wid>>2)*64, wn = (wid&3)*32;

  // ldmatrix per-lane address components (swizzle: 16B chunk ^= (row>>1)&3)
  const int ar   = (lane&7) + ((lane>>3)&1)*8;   // A row within m16 tile
  const int acb  = (lane>>4)&1;                  // A 16B-chunk base
  const int aswz = (ar>>1)&3;
  const int br   = lane&7;                       // B row within n8 tile
  const int bcb  = (lane>>3)&1;
  const int bswz = (br>>1)&3;

  float f1[4][4][4]; float f2[4][4][4];
#pragma unroll
  for (int i=0;i<4;i++)
#pragma unroll
    for (int j=0;j<4;j++)
#pragma unroll
      for (int k=0;k<4;k++){ f1[i][j][k]=0.f; if (MODE==0) f2[i][j][k]=0.f; }

  load_stage<NB,KTOT>(sb, A, sA, B1, B2, m0, n0, 0, tid);

#pragma unroll 1
  for (int g=0; g<NG; ++g){
    const int s = g&1;
    if (g+1 < NG){
      load_stage<NB,KTOT>(sb + (s^1)*STAGE, A, sA, B1, B2, m0, n0, g+1, tid);
      asm volatile("cp.async.wait_group 1;");
    } else {
      asm volatile("cp.async.wait_group 0;");
    }
    __syncthreads();

    const uint32_t st = sb + s*STAGE;
    const float* sf = (const float*)(smem + s*STAGE + 128*64*(1+NB));
    float sc[4][2];
#pragma unroll
    for (int mt=0;mt<4;mt++){
      sc[mt][0] = sf[wm + mt*16 + (lane>>2)];
      sc[mt][1] = sf[wm + mt*16 + (lane>>2) + 8];
    }

    uint32_t a[2][4][4];
#pragma unroll
    for (int ks=0;ks<2;ks++)
#pragma unroll
      for (int mt=0;mt<4;mt++)
        ldsm4(a[ks][mt], st + (wm+mt*16+ar)*64 + (((acb+ks*2)^aswz)<<4));

    // ---- GEMM vs B1 ----
    {
      uint32_t bfr[2][4][2];
#pragma unroll
      for (int ks=0;ks<2;ks++)
#pragma unroll
        for (int nt=0;nt<4;nt++)
          ldsm2(bfr[ks][nt], st + 128*64 + (wn+nt*8+br)*64 + (((bcb+ks*2)^bswz)<<4));
#pragma unroll
      for (int mt=0;mt<4;mt++)
#pragma unroll
        for (int nt=0;nt<4;nt++){
          int d[4]={0,0,0,0};
          imma(d, a[0][mt], bfr[0][nt]);
          imma(d, a[1][mt], bfr[1][nt]);
          f1[mt][nt][0] += sc[mt][0]*(float)d[0];
          f1[mt][nt][1] += sc[mt][0]*(float)d[1];
          f1[mt][nt][2] += sc[mt][1]*(float)d[2];
          f1[mt][nt][3] += sc[mt][1]*(float)d[3];
        }
    }
    // ---- GEMM vs B2 (MODE 0 only) ----
    if (MODE==0){
      uint32_t bfr[2][4][2];
#pragma unroll
      for (int ks=0;ks<2;ks++)
#pragma unroll
        for (int nt=0;nt<4;nt++)
          ldsm2(bfr[ks][nt], st + 128*64*2 + (wn+nt*8+br)*64 + (((bcb+ks*2)^bswz)<<4));
#pragma unroll
      for (int mt=0;mt<4;mt++)
#pragma unroll
        for (int nt=0;nt<4;nt++){
          int d[4]={0,0,0,0};
          imma(d, a[0][mt], bfr[0][nt]);
          imma(d, a[1][mt], bfr[1][nt]);
          f2[mt][nt][0] += sc[mt][0]*(float)d[0];
          f2[mt][nt][1] += sc[mt][0]*(float)d[1];
          f2[mt][nt][2] += sc[mt][1]*(float)d[2];
          f2[mt][nt][3] += sc[mt][1]*(float)d[3];
        }
    }
    __syncthreads();
  }

  // ---------------- epilogue ----------------
  if (MODE==0){
    const float c1 = g_wscale[0], c2 = g_wscale[1];
#pragma unroll
    for (int mt=0;mt<4;mt++)
#pragma unroll
      for (int nt=0;nt<4;nt++)
#pragma unroll
        for (int hr=0;hr<2;hr++){
          int r    = m0 + wm + mt*16 + (lane>>2) + hr*8;
          int cidx = n0 + wn + nt*8 + (lane&3)*2;
          float u0 = c1*f1[mt][nt][hr*2+0], u1 = c1*f1[mt][nt][hr*2+1];
          float v0 = c2*f2[mt][nt][hr*2+0], v1 = c2*f2[mt][nt][hr*2+1];
          float h0 = u0/(1.f+expf(-u0))*v0;
          float h1 = u1/(1.f+expf(-u1))*v1;
          *(float2*)&g_h[(size_t)r*DFF + cidx] = make_float2(h0,h1);
        }
  } else {
    const float c3 = g_wscale[2];
#pragma unroll
    for (int mt=0;mt<4;mt++)
#pragma unroll
      for (int nt=0;nt<4;nt++)
#pragma unroll
        for (int hr=0;hr<2;hr++){
          int r    = m0 + wm + mt*16 + (lane>>2) + hr*8;
          int cidx = n0 + wn + nt*8 + (lane&3)*2;
          *(float2*)&C[(size_t)r*DMODEL + cidx] =
              make_float2(c3*f1[mt][nt][hr*2+0], c3*f1[mt][nt][hr*2+1]);
        }
  }
}

// ---------------- host launcher ---------------------------------------------
extern "C" void kernel_launch(void* const* d_in, const int* in_sizes, int n_in,
                              void* d_out, int out_size)
{
  const float* x  = (const float*)d_in[0];
  const float* w1 = (const float*)d_in[1];
  const float* w2 = (const float*)d_in[2];
  const float* w3 = (const float*)d_in[3];

  void *w1s,*w2s,*w3s,*xq,*sx,*h,*hq,*sh;
  cudaGetSymbolAddress(&w1s, g_w1s);
  cudaGetSymbolAddress(&w2s, g_w2s);
  cudaGetSymbolAddress(&w3s, g_w3s);
  cudaGetSymbolAddress(&xq , g_xq );
  cudaGetSymbolAddress(&sx , g_sx );
  cudaGetSymbolAddress(&h  , g_h  );
  cudaGetSymbolAddress(&hq , g_hq );
  cudaGetSymbolAddress(&sh , g_sh );

  const int NW12 = DFF*DMODEL;     // 16.7M
  const int NW3  = DMODEL*DFF;

  // mean|w| (deterministic two-pass), sequential reuse of g_partial
  absmean_partial<<<2048,256>>>((const float4*)w1, NW12/4);
  absmean_final  <<<1,256>>>(2048, 1.0f/(float)NW12, 0);
  absmean_partial<<<2048,256>>>((const float4*)w2, NW12/4);
  absmean_final  <<<1,256>>>(2048, 1.0f/(float)NW12, 1);
  absmean_partial<<<2048,256>>>((const float4*)w3, NW3/4);
  absmean_final  <<<1,256>>>(2048, 1.0f/(float)NW3, 2);

  // sign-pack weights
  sign_kernel<<<4096,256>>>((const float4*)w1, (char4*)w1s, NW12/4);
  sign_kernel<<<4096,256>>>((const float4*)w2, (char4*)w2s, NW12/4);
  sign_kernel<<<4096,256>>>((const float4*)w3, (char4*)w3s, NW3/4);

  // quantize x
  quant_kernel<<<2048,256>>>((const float2*)x, (char2*)xq, (float*)sx, MTOK*NGX);

  // fused GEMM1+2 + SwiGLU -> g_h
  constexpr int SM0 = 2*(128*64*3 + 128*4);
  cudaFuncSetAttribute(gemm_s8<0,DMODEL>, cudaFuncAttributeMaxDynamicSharedMemorySize, SM0);
  gemm_s8<0,DMODEL><<<dim3(DFF/128, MTOK/128), 256, SM0>>>(
      (const int8_t*)xq, (const float*)sx,
      (const int8_t*)w1s, (const int8_t*)w2s, nullptr);

  // quantize h
  quant_kernel<<<4096,256>>>((const float2*)h, (char2*)hq, (float*)sh, MTOK*NGH);

  // GEMM3 -> out
  constexpr int SM1 = 2*(128*64*2 + 128*4);
  cudaFuncSetAttribute(gemm_s8<1,DFF>, cudaFuncAttributeMaxDynamicSharedMemorySize, SM1);
  gemm_s8<1,DFF><<<dim3(DMODEL/128, MTOK/128), 256, SM1>>>(
      (const int8_t*)hq, (const float*)sh,
      (const int8_t*)w3s, nullptr, (float*)d_out);
}